// round 7
// baseline (speedup 1.0000x reference)
#include <cuda_runtime.h>
#include <cuda_bf16.h>

// Problem constants
#define B 4
#define P 12000
#define C 64
#define H 512
#define W 512
#define TILE_X 128
#define SLOT_CAP 20     // staged rows per tile (mean occ 5.9; +6 sigma)
#define NT (B * H * (W / TILE_X))   // 8192 tiles
#define NBLK (148 * 12)             // fully resident: 12 x 160 thr, ~12KB smem

// Winner pillar map per output pixel, encoded as (p+1); 0 = empty.
// Zero-initialized at module load; gather restores strips to 0
// (read-then-clear by the SAME thread => ordered), so the all-zeros
// invariant holds before every kernel_launch call / graph replay.
__device__ int g_winner[B * H * W];

// Kernel 1: one thread per (b, p). Reference semantics: sequential .at[].set
// means the LARGEST pillar index wins per pixel -> atomicMax on (p+1).
__global__ void scatter_winner_kernel(const int* __restrict__ coords) {
    int i = blockIdx.x * blockDim.x + threadIdx.x;   // i = b*P + p
    if (i >= B * P) return;
    int b = i / P;
    int p = i - b * P;
    int4 c4 = reinterpret_cast<const int4*>(coords)[i];  // (batch, y, x, z)
    int y = c4.y;
    int x = c4.z;
    if ((unsigned)x < (unsigned)W && (unsigned)y < (unsigned)H) {
        atomicMax(&g_winner[(b * H + y) * W + x], p + 1);
    }
}

// Kernel 2: persistent producer/consumer pipeline.
//   warps 0-3 (128 thr): emit tile k from smem buffer `buf`
//   warp 4 (producer):   prepare tile k+gridDim into buffer `buf^1`
//                        (winner LDG + clear, ballot compaction, feature
//                         staging) — latency hidden under the emit burst.
__global__ __launch_bounds__(160) void gather_out_kernel(
    const float* __restrict__ feat, float* __restrict__ out) {
    __shared__ int   s_slot[2][TILE_X];  // >=0: slot | -1: empty | <=-2: pid=-(s)-2
    __shared__ int   s_pid[2][SLOT_CAP];
    __shared__ int   s_n[2];
    __shared__ float s_feat[2][SLOT_CAP * 65];   // padded rows
    __shared__ float s_zero[64];

    const int tid  = threadIdx.x;
    const int lane = tid & 31;
    const int wid  = tid >> 5;
    const bool producer = (wid == 4);

    if (tid < 64) s_zero[tid] = 0.0f;

    // -------- producer routine (inlined twice) --------
    // tile t -> (b, y, xt):  b = t>>11, y = (t>>2)&511, xt = t&3
#define PRODUCE(T, BF)                                                        \
    do {                                                                      \
        const int t_  = (T);                                                  \
        const int b_  = t_ >> 11;                                             \
        const int y_  = (t_ >> 2) & (H - 1);                                  \
        const int xt_ = t_ & 3;                                               \
        int4* wrow4 = reinterpret_cast<int4*>(                                \
            g_winner + (b_ * H + y_) * W + xt_ * TILE_X);                     \
        int4 w4 = wrow4[lane];                                                \
        wrow4[lane] = make_int4(0, 0, 0, 0); /* same thread => ordered */     \
        const int wv_[4] = {w4.x, w4.y, w4.z, w4.w};                          \
        const unsigned lt_ = (1u << lane) - 1u;                               \
        int base_ = 0;                                                        \
        _Pragma("unroll")                                                     \
        for (int j = 0; j < 4; ++j) {                                         \
            const bool occ_ = (wv_[j] > 0);                                   \
            const unsigned m_ = __ballot_sync(0xFFFFFFFFu, occ_);             \
            int s_ = -1;                                                      \
            if (occ_) {                                                       \
                int sl_ = base_ + __popc(m_ & lt_);                           \
                if (sl_ < SLOT_CAP) { s_pid[BF][sl_] = wv_[j] - 1; s_ = sl_; }\
                else                { s_ = -(wv_[j] + 1); }                   \
            }                                                                 \
            s_slot[BF][lane * 4 + j] = s_;                                    \
            base_ += __popc(m_);                                              \
        }                                                                     \
        if (lane == 0) s_n[BF] = base_;                                       \
        __syncwarp();                                                         \
        const int ns_ = min(base_, SLOT_CAP);                                 \
        const float4* fb4_ = reinterpret_cast<const float4*>(                 \
            feat + (size_t)b_ * P * C);                                       \
        for (int i = lane; i < ns_ * (C / 4); i += 32) {                      \
            int sl_ = i >> 4;                                                 \
            int q_  = i & 15;                                                 \
            float4 v_ = __ldg(&fb4_[(size_t)s_pid[BF][sl_] * (C / 4) + q_]);  \
            float* d_ = &s_feat[BF][sl_ * 65 + q_ * 4];                       \
            d_[0] = v_.x; d_[1] = v_.y; d_[2] = v_.z; d_[3] = v_.w;           \
        }                                                                     \
    } while (0)

    int tile = blockIdx.x;
    int buf  = 0;

    if (producer && tile < NT) PRODUCE(tile, 0);
    __syncthreads();

    for (; tile < NT; tile += gridDim.x) {
        if (producer) {
            const int nt = tile + gridDim.x;
            if (nt < NT) PRODUCE(nt, buf ^ 1);
        } else {
            // -------- emit tile from buffer `buf` --------
            const int b  = tile >> 11;
            const int y  = (tile >> 2) & (H - 1);
            const int xt = tile & 3;
            const int c0 = wid;                  // 0..3
            const int px = lane * 4;

            const int s0 = s_slot[buf][px + 0];
            const int s1 = s_slot[buf][px + 1];
            const int s2 = s_slot[buf][px + 2];
            const int s3 = s_slot[buf][px + 3];

            float4* dst = reinterpret_cast<float4*>(out)
                        + ((size_t)(b * C + c0) * H + y) * (W / 4)
                        + xt * (TILE_X / 4) + lane;
            const size_t step = (size_t)4 * H * (W / 4);   // c += 4

            if (s_n[buf] <= SLOT_CAP) {
                const float* fb = s_feat[buf];
                const float* f0 = (s0 >= 0) ? fb + s0 * 65 : s_zero;
                const float* f1 = (s1 >= 0) ? fb + s1 * 65 : s_zero;
                const float* f2 = (s2 >= 0) ? fb + s2 * 65 : s_zero;
                const float* f3 = (s3 >= 0) ? fb + s3 * 65 : s_zero;
                #pragma unroll 8
                for (int it = 0; it < 16; ++it) {
                    const int c = c0 + 4 * it;
                    float4 v = make_float4(f0[c], f1[c], f2[c], f3[c]);
                    __stcs(dst, v);
                    dst += step;
                }
            } else {
                // Statistically-never slow path (>SLOT_CAP occupied px).
                const float* featb = feat + (size_t)b * P * C;
                #pragma unroll 4
                for (int it = 0; it < 16; ++it) {
                    const int c = c0 + 4 * it;
                    float4 v;
                    v.x = (s0 >= 0) ? s_feat[buf][s0 * 65 + c]
                        : (s0 == -1) ? 0.0f : featb[(size_t)(-s0 - 2) * C + c];
                    v.y = (s1 >= 0) ? s_feat[buf][s1 * 65 + c]
                        : (s1 == -1) ? 0.0f : featb[(size_t)(-s1 - 2) * C + c];
                    v.z = (s2 >= 0) ? s_feat[buf][s2 * 65 + c]
                        : (s2 == -1) ? 0.0f : featb[(size_t)(-s2 - 2) * C + c];
                    v.w = (s3 >= 0) ? s_feat[buf][s3 * 65 + c]
                        : (s3 == -1) ? 0.0f : featb[(size_t)(-s3 - 2) * C + c];
                    __stcs(dst, v);
                    dst += step;
                }
            }
        }
        __syncthreads();
        buf ^= 1;
    }
#undef PRODUCE
}

extern "C" void kernel_launch(void* const* d_in, const int* in_sizes, int n_in,
                              void* d_out, int out_size) {
    const float* feat   = (const float*)d_in[0];   // [B, P, C] fp32
    const int*   coords = (const int*)d_in[1];     // [B, P, 4] int32
    float* out = (float*)d_out;                    // [B, C, H, W] fp32

    scatter_winner_kernel<<<(B * P + 255) / 256, 256>>>(coords);

    gather_out_kernel<<<NBLK, 160>>>(feat, out);
}